// round 4
// baseline (speedup 1.0000x reference)
#include <cuda_runtime.h>
#include <cstdint>

// DbrxRouter: x[T,H] fp32 @ W[E,H]^T -> logits[T,E=16]; softmax -> top4 -> /sum(top4)
// Outputs concatenated float32: weights [T,4] then expert indices [T,4] (as float).
//
// Layout: warp handles 4 tokens x 16 experts. Experts split across half-warps
// (lanes 0-15: experts 0-7, lanes 16-31: experts 8-15); each half strides H by
// 16 float4s. Halves load identical x addresses (intra-warp broadcast, free).
// Packed f32x2 FMAs. 2-deep software pipeline for ~24 LDGs in flight per warp.

#define NE  16
#define TOK 4
#define EPL 8   // experts per half-warp

__device__ __forceinline__ void fma2(unsigned long long& d,
                                     unsigned long long a,
                                     unsigned long long b) {
    asm("fma.rn.f32x2 %0, %1, %2, %0;" : "+l"(d) : "l"(a), "l"(b));
}
__device__ __forceinline__ float lo_f(unsigned long long v) {
    return __uint_as_float((unsigned)(v & 0xffffffffull));
}
__device__ __forceinline__ float hi_f(unsigned long long v) {
    return __uint_as_float((unsigned)(v >> 32));
}

__global__ __launch_bounds__(128, 3)
void router_kernel(const float* __restrict__ x, const float* __restrict__ w,
                   float* __restrict__ out, int T, int H4, int idx_off)
{
    const int warp = blockIdx.x * (blockDim.x >> 5) + (threadIdx.x >> 5);
    const int lane = threadIdx.x & 31;
    const int sub  = lane & 15;          // position within half-warp
    const int half = lane >> 4;          // 0: experts 0-7, 1: experts 8-15
    const int t0 = warp * TOK;
    if (t0 >= T) return;

    size_t r[TOK];
    #pragma unroll
    for (int t = 0; t < TOK; t++)
        r[t] = (size_t)min(t0 + t, T - 1) * H4;

    const ulonglong2* __restrict__ x2 = reinterpret_cast<const ulonglong2*>(x);
    const ulonglong2* __restrict__ w2 = reinterpret_cast<const ulonglong2*>(w);
    const size_t wbase = (size_t)(half * EPL) * H4;

    unsigned long long acc[TOK][EPL];
    #pragma unroll
    for (int t = 0; t < TOK; t++)
        #pragma unroll
        for (int e = 0; e < EPL; e++)
            acc[t][e] = 0ull;

    // ---- software-pipelined mainloop: stride 16 float4s per half-warp ----
    const int NIT = H4 >> 4;             // 1536/16 = 96 iterations
    int i = sub;

    ulonglong2 a[TOK], b[EPL];
    #pragma unroll
    for (int t = 0; t < TOK; t++) a[t] = x2[r[t] + i];
    #pragma unroll
    for (int e = 0; e < EPL; e++) b[e] = w2[wbase + (size_t)e * H4 + i];

    for (int it = 0; it < NIT - 1; ++it) {
        i += 16;
        ulonglong2 an[TOK], bn[EPL];
        #pragma unroll
        for (int t = 0; t < TOK; t++) an[t] = x2[r[t] + i];
        #pragma unroll
        for (int e = 0; e < EPL; e++) bn[e] = w2[wbase + (size_t)e * H4 + i];

        #pragma unroll
        for (int e = 0; e < EPL; e++)
            #pragma unroll
            for (int t = 0; t < TOK; t++) {
                fma2(acc[t][e], a[t].x, b[e].x);
                fma2(acc[t][e], a[t].y, b[e].y);
            }

        #pragma unroll
        for (int t = 0; t < TOK; t++) a[t] = an[t];
        #pragma unroll
        for (int e = 0; e < EPL; e++) b[e] = bn[e];
    }
    // final (un-prefetched) iteration
    #pragma unroll
    for (int e = 0; e < EPL; e++)
        #pragma unroll
        for (int t = 0; t < TOK; t++) {
            fma2(acc[t][e], a[t].x, b[e].x);
            fma2(acc[t][e], a[t].y, b[e].y);
        }

    // ---- collapse packed halves, reduce within each 16-lane half ----
    float lg[TOK][EPL];
    #pragma unroll
    for (int t = 0; t < TOK; t++)
        #pragma unroll
        for (int e = 0; e < EPL; e++)
            lg[t][e] = lo_f(acc[t][e]) + hi_f(acc[t][e]);

    #pragma unroll
    for (int off = 8; off >= 1; off >>= 1)
        #pragma unroll
        for (int t = 0; t < TOK; t++)
            #pragma unroll
            for (int e = 0; e < EPL; e++)
                lg[t][e] += __shfl_xor_sync(0xffffffffu, lg[t][e], off);

    // Each lane selects its token's 8 half-local experts (static selects).
    float sel[EPL];
    #pragma unroll
    for (int e = 0; e < EPL; e++) {
        float v = lg[0][e];
        if (sub == 1) v = lg[1][e];
        if (sub == 2) v = lg[2][e];
        if (sub == 3) v = lg[3][e];
        sel[e] = v;
    }
    // Exchange halves: lane l (<4) gets experts 8-15 from lane l+16.
    float oth[EPL];
    #pragma unroll
    for (int e = 0; e < EPL; e++)
        oth[e] = __shfl_xor_sync(0xffffffffu, sel[e], 16);

    const int token = t0 + sub;
    if (lane < 4 && token < T) {
        float mylg[NE];
        #pragma unroll
        for (int e = 0; e < EPL; e++) { mylg[e] = sel[e]; mylg[EPL + e] = oth[e]; }

        // Top-4, stable (strict '>' picks lowest index on ties, matching jax).
        unsigned mask = 0;
        float tw[4];
        int   ti[4];
        #pragma unroll
        for (int k = 0; k < 4; k++) {
            float best = -3.402823466e38f;
            int bi = 0;
            #pragma unroll
            for (int e = 0; e < NE; e++) {
                bool ok = (((mask >> e) & 1u) == 0u) && (mylg[e] > best);
                if (ok) { best = mylg[e]; bi = e; }
            }
            tw[k] = best; ti[k] = bi;
            mask |= (1u << bi);
        }
        // Softmax denominator cancels against p=1 renorm.
        const float m = tw[0];
        float s = 0.f;
        #pragma unroll
        for (int k = 0; k < 4; k++) { tw[k] = expf(tw[k] - m); s += tw[k]; }
        const float inv = 1.0f / s;
        #pragma unroll
        for (int k = 0; k < 4; k++) {
            out[token * 4 + k] = tw[k] * inv;
            if (idx_off >= 0) out[idx_off + token * 4 + k] = (float)ti[k];
        }
    }
}

extern "C" void kernel_launch(void* const* d_in, const int* in_sizes, int n_in,
                              void* d_out, int out_size)
{
    const float* x = (const float*)d_in[0];
    const float* w = (const float*)d_in[1];

    const int H  = in_sizes[1] / NE;     // 6144
    const int T  = in_sizes[0] / H;      // 8192
    const int H4 = H / 4;                // 1536 float4 per row

    const int idx_off = (out_size >= T * 8) ? (T * 4) : -1;

    const int warps  = (T + 3) / 4;      // 2048
    const int blocks = (warps + 3) / 4;  // 4 warps (128 threads) per block
    router_kernel<<<blocks, 128>>>(x, w, (float*)d_out, T, H4, idx_off);
}

// round 7
// speedup vs baseline: 1.5453x; 1.5453x over previous
#include <cuda_runtime.h>
#include <cstdint>

// DbrxRouter: x[T,H] fp32 @ W[E=16,H]^T -> logits; softmax -> top4 -> /sum(top4)
// Outputs concatenated float32: weights [T,4] then expert indices [T,4] (as float).
//
// Warp = 4 tokens x 16 experts. Quarter-warp split: 8-lane group q owns experts
// 4q..4q+3 and strides H by 8 float4s. All quarters load identical x addresses
// (one 128B line per x LDG, broadcast). acc is 32 regs -> high occupancy.
// Plain loop + unroll; ptxas schedules the MLP. 512 CTAs @ 4/SM = single wave.

#define NE  16
#define TOK 4
#define EPQ 4   // experts per quarter-warp

__device__ __forceinline__ void fma2(unsigned long long& d,
                                     unsigned long long a,
                                     unsigned long long b) {
    asm("fma.rn.f32x2 %0, %1, %2, %0;" : "+l"(d) : "l"(a), "l"(b));
}
__device__ __forceinline__ float lo_f(unsigned long long v) {
    return __uint_as_float((unsigned)(v & 0xffffffffull));
}
__device__ __forceinline__ float hi_f(unsigned long long v) {
    return __uint_as_float((unsigned)(v >> 32));
}

__global__ __launch_bounds__(128, 4)
void router_kernel(const float* __restrict__ x, const float* __restrict__ w,
                   float* __restrict__ out, int T, int H4, int idx_off)
{
    const int warp = blockIdx.x * (blockDim.x >> 5) + (threadIdx.x >> 5);
    const int lane = threadIdx.x & 31;
    const int qid  = lane >> 3;          // quarter-warp id: experts 4q..4q+3
    const int sub  = lane & 7;           // position within quarter
    const int t0   = warp * TOK;
    if (t0 >= T) return;

    size_t r[TOK];
    #pragma unroll
    for (int t = 0; t < TOK; t++)
        r[t] = (size_t)min(t0 + t, T - 1) * H4;

    const ulonglong2* __restrict__ x2 = reinterpret_cast<const ulonglong2*>(x);
    const ulonglong2* __restrict__ w2 = reinterpret_cast<const ulonglong2*>(w);

    // Base of this quarter's 4 expert rows; inner-loop addressing is
    // wq[e*H4 + i] with constant e -> folds into LDG immediate offsets.
    const ulonglong2* __restrict__ wq = w2 + (size_t)qid * EPQ * H4;

    unsigned long long acc[TOK][EPQ];
    #pragma unroll
    for (int t = 0; t < TOK; t++)
        #pragma unroll
        for (int e = 0; e < EPQ; e++)
            acc[t][e] = 0ull;

    // Mainloop: 192 iterations (H4=1536, stride 8 per quarter-warp).
    // Per iter: 4 x LDG (1 line each, broadcast) + 4 W LDG (4 lines each),
    // 32 fma2 per thread. Unroll 4 lets ptxas batch 32 LDGs for MLP.
    #pragma unroll 4
    for (int i = sub; i < H4; i += 8) {
        ulonglong2 a0 = x2[r[0] + i];
        ulonglong2 a1 = x2[r[1] + i];
        ulonglong2 a2 = x2[r[2] + i];
        ulonglong2 a3 = x2[r[3] + i];
        #pragma unroll
        for (int e = 0; e < EPQ; e++) {
            const ulonglong2 b = wq[(size_t)e * H4 + i];
            fma2(acc[0][e], a0.x, b.x); fma2(acc[0][e], a0.y, b.y);
            fma2(acc[1][e], a1.x, b.x); fma2(acc[1][e], a1.y, b.y);
            fma2(acc[2][e], a2.x, b.x); fma2(acc[2][e], a2.y, b.y);
            fma2(acc[3][e], a3.x, b.x); fma2(acc[3][e], a3.y, b.y);
        }
    }

    // Collapse packed halves; reduce within each 8-lane quarter (xor 4,2,1).
    float lg[TOK][EPQ];
    #pragma unroll
    for (int t = 0; t < TOK; t++)
        #pragma unroll
        for (int e = 0; e < EPQ; e++)
            lg[t][e] = lo_f(acc[t][e]) + hi_f(acc[t][e]);

    #pragma unroll
    for (int off = 4; off >= 1; off >>= 1)
        #pragma unroll
        for (int t = 0; t < TOK; t++)
            #pragma unroll
            for (int e = 0; e < EPQ; e++)
                lg[t][e] += __shfl_xor_sync(0xffffffffu, lg[t][e], off);

    // Lane sub==t within each quarter holds token t's 4 quarter-local experts.
    float sel[EPQ];
    #pragma unroll
    for (int e = 0; e < EPQ; e++) {
        float v = lg[0][e];
        if (sub == 1) v = lg[1][e];
        if (sub == 2) v = lg[2][e];
        if (sub == 3) v = lg[3][e];
        sel[e] = v;
    }

    // Lane l (<4) gathers token l's 16 experts from lanes {8q + l}.
    float mylg[NE];
    #pragma unroll
    for (int q = 0; q < 4; q++)
        #pragma unroll
        for (int e = 0; e < EPQ; e++)
            mylg[q * EPQ + e] = __shfl_sync(0xffffffffu, sel[e], q * 8 + (lane & 7));

    const int token = t0 + lane;
    if (lane < 4 && token < T) {
        // Top-4, stable (strict '>' picks lowest index on ties, matching jax).
        unsigned mask = 0;
        float tw[4];
        int   ti[4];
        #pragma unroll
        for (int k = 0; k < 4; k++) {
            float best = -3.402823466e38f;
            int bi = 0;
            #pragma unroll
            for (int e = 0; e < NE; e++) {
                bool ok = (((mask >> e) & 1u) == 0u) && (mylg[e] > best);
                if (ok) { best = mylg[e]; bi = e; }
            }
            tw[k] = best; ti[k] = bi;
            mask |= (1u << bi);
        }
        // Softmax denominator cancels against p=1 renorm.
        const float m = tw[0];
        float s = 0.f;
        #pragma unroll
        for (int k = 0; k < 4; k++) { tw[k] = expf(tw[k] - m); s += tw[k]; }
        const float inv = 1.0f / s;
        #pragma unroll
        for (int k = 0; k < 4; k++) {
            out[token * 4 + k] = tw[k] * inv;
            if (idx_off >= 0) out[idx_off + token * 4 + k] = (float)ti[k];
        }
    }
}

extern "C" void kernel_launch(void* const* d_in, const int* in_sizes, int n_in,
                              void* d_out, int out_size)
{
    const float* x = (const float*)d_in[0];
    const float* w = (const float*)d_in[1];

    const int H  = in_sizes[1] / NE;     // 6144
    const int T  = in_sizes[0] / H;      // 8192
    const int H4 = H / 4;                // 1536 float4 per row

    const int idx_off = (out_size >= T * 8) ? (T * 4) : -1;

    const int warps  = (T + 3) / 4;      // 2048
    const int blocks = (warps + 3) / 4;  // 512 CTAs of 128 threads
    router_kernel<<<blocks, 128>>>(x, w, (float*)d_out, T, H4, idx_off);
}

// round 8
// speedup vs baseline: 1.9236x; 1.2448x over previous
#include <cuda_runtime.h>
#include <cstdint>

// DbrxRouter: x[T,H] fp32 @ W[E=16,H]^T -> logits; softmax -> top4 -> /sum(top4)
// Outputs concatenated float32: weights [T,4] then expert indices [T,4] (as float).
//
// Warp = 4 tokens x 16 experts (quarter-warp expert split, 4 experts/quarter).
// x (the DRAM stream) is prefetched via cp.async.cg into a WARP-PRIVATE smem
// ring, 8 chunks (64 floats/token) deep -> DRAM latency fully hidden with zero
// register cost and zero CTA barriers. W read by direct LDG (L1/L2 resident).

#define NE      16
#define TOK     4
#define EPQ     4
#define STAGES  8
#define CH4     16            // float4 per chunk per token (64 floats)

__device__ __forceinline__ void fma2(unsigned long long& d,
                                     unsigned long long a,
                                     unsigned long long b) {
    asm("fma.rn.f32x2 %0, %1, %2, %0;" : "+l"(d) : "l"(a), "l"(b));
}
__device__ __forceinline__ float lo_f(unsigned long long v) {
    return __uint_as_float((unsigned)(v & 0xffffffffull));
}
__device__ __forceinline__ float hi_f(unsigned long long v) {
    return __uint_as_float((unsigned)(v >> 32));
}
__device__ __forceinline__ void cp16(uint32_t dst, const void* src) {
    asm volatile("cp.async.cg.shared.global [%0], [%1], 16;"
                 :: "r"(dst), "l"(src) : "memory");
}

__global__ __launch_bounds__(128, 4)
void router_kernel(const float* __restrict__ x, const float* __restrict__ w,
                   float* __restrict__ out, int T, int H4, int idx_off)
{
    // Warp-private x staging: [warp][stage][token][CH4 float4] = 32 KB/CTA.
    __shared__ __align__(16) ulonglong2 xs[4][STAGES][TOK * CH4];

    const int wid  = threadIdx.x >> 5;
    const int lane = threadIdx.x & 31;
    const int qid  = lane >> 3;          // quarter: experts 4q..4q+3
    const int sub  = lane & 7;
    const int warp = blockIdx.x * 4 + wid;
    const int t0   = warp * TOK;
    if (t0 >= T) return;

    const size_t r0 = (size_t)min(t0 + 0, T - 1) * H4;
    const size_t r1 = (size_t)min(t0 + 1, T - 1) * H4;
    const size_t r2 = (size_t)min(t0 + 2, T - 1) * H4;
    const size_t r3 = (size_t)min(t0 + 3, T - 1) * H4;

    const ulonglong2* __restrict__ x2 = reinterpret_cast<const ulonglong2*>(x);
    const ulonglong2* __restrict__ w2 = reinterpret_cast<const ulonglong2*>(w);
    const ulonglong2* __restrict__ wq = w2 + (size_t)qid * EPQ * H4;

    // Copy mapping: 64 x 16B per stage, 2 per lane.
    //   opA: token tA = lane>>4 (0/1), off = lane&15
    //   opB: token tA+2,                off = lane&15
    const int offc   = lane & 15;
    const size_t rA  = (lane & 16) ? r1 : r0;
    const size_t rB  = (lane & 16) ? r3 : r2;
    const int   tA   = lane >> 4;

    uint32_t smem_base = (uint32_t)__cvta_generic_to_shared(&xs[wid][0][0]);
    const uint32_t dA0 = smem_base + (uint32_t)((tA * CH4 + offc) * 16);
    const uint32_t dB0 = dA0 + 2 * CH4 * 16;
    const uint32_t stage_bytes = TOK * CH4 * 16;   // 1024

    const int NCH = H4 / CH4;            // 96 chunks

    // Prologue: fill STAGES-1 stages.
    #pragma unroll
    for (int p = 0; p < STAGES - 1; ++p) {
        const uint32_t sb = (uint32_t)(p & (STAGES - 1)) * stage_bytes;
        cp16(dA0 + sb, x2 + rA + p * CH4 + offc);
        cp16(dB0 + sb, x2 + rB + p * CH4 + offc);
        asm volatile("cp.async.commit_group;" ::: "memory");
    }

    unsigned long long acc[TOK][EPQ];
    #pragma unroll
    for (int t = 0; t < TOK; t++)
        #pragma unroll
        for (int e = 0; e < EPQ; e++)
            acc[t][e] = 0ull;

    const ulonglong2* xsw = &xs[wid][0][0];

    #pragma unroll 1
    for (int c = 0; c < NCH; ++c) {
        // Issue copy for chunk c+STAGES-1 (or an empty group to keep counts uniform).
        const int cf = c + STAGES - 1;
        if (cf < NCH) {
            const uint32_t sb = (uint32_t)(cf & (STAGES - 1)) * stage_bytes;
            cp16(dA0 + sb, x2 + rA + cf * CH4 + offc);
            cp16(dB0 + sb, x2 + rB + cf * CH4 + offc);
        }
        asm volatile("cp.async.commit_group;" ::: "memory");
        // Chunk c's group is complete when <= STAGES-2 groups remain in flight.
        asm volatile("cp.async.wait_group %0;" :: "n"(STAGES - 2) : "memory");
        __syncwarp();

        const ulonglong2* xc = xsw + (size_t)(c & (STAGES - 1)) * (TOK * CH4);
        #pragma unroll
        for (int j = 0; j < 2; ++j) {
            const int jo = j * 8 + sub;
            const ulonglong2 a0 = xc[0 * CH4 + jo];
            const ulonglong2 a1 = xc[1 * CH4 + jo];
            const ulonglong2 a2 = xc[2 * CH4 + jo];
            const ulonglong2 a3 = xc[3 * CH4 + jo];
            const size_t i = (size_t)c * CH4 + jo;
            #pragma unroll
            for (int e = 0; e < EPQ; e++) {
                const ulonglong2 b = wq[(size_t)e * H4 + i];
                fma2(acc[0][e], a0.x, b.x); fma2(acc[0][e], a0.y, b.y);
                fma2(acc[1][e], a1.x, b.x); fma2(acc[1][e], a1.y, b.y);
                fma2(acc[2][e], a2.x, b.x); fma2(acc[2][e], a2.y, b.y);
                fma2(acc[3][e], a3.x, b.x); fma2(acc[3][e], a3.y, b.y);
            }
        }
    }

    // Collapse packed halves; reduce within each 8-lane quarter (xor 4,2,1).
    float lg[TOK][EPQ];
    #pragma unroll
    for (int t = 0; t < TOK; t++)
        #pragma unroll
        for (int e = 0; e < EPQ; e++)
            lg[t][e] = lo_f(acc[t][e]) + hi_f(acc[t][e]);

    #pragma unroll
    for (int off = 4; off >= 1; off >>= 1)
        #pragma unroll
        for (int t = 0; t < TOK; t++)
            #pragma unroll
            for (int e = 0; e < EPQ; e++)
                lg[t][e] += __shfl_xor_sync(0xffffffffu, lg[t][e], off);

    // Lane sub==t within each quarter holds token t's 4 quarter-local experts.
    float sel[EPQ];
    #pragma unroll
    for (int e = 0; e < EPQ; e++) {
        float v = lg[0][e];
        if (sub == 1) v = lg[1][e];
        if (sub == 2) v = lg[2][e];
        if (sub == 3) v = lg[3][e];
        sel[e] = v;
    }

    // Lane l (<4) gathers token l's 16 experts from lanes {8q + l}.
    float mylg[NE];
    #pragma unroll
    for (int q = 0; q < 4; q++)
        #pragma unroll
        for (int e = 0; e < EPQ; e++)
            mylg[q * EPQ + e] = __shfl_sync(0xffffffffu, sel[e], q * 8 + (lane & 7));

    const int token = t0 + lane;
    if (lane < 4 && token < T) {
        // Top-4, stable (strict '>' picks lowest index on ties, matching jax).
        unsigned mask = 0;
        float tw[4];
        int   ti[4];
        #pragma unroll
        for (int k = 0; k < 4; k++) {
            float best = -3.402823466e38f;
            int bi = 0;
            #pragma unroll
            for (int e = 0; e < NE; e++) {
                bool ok = (((mask >> e) & 1u) == 0u) && (mylg[e] > best);
                if (ok) { best = mylg[e]; bi = e; }
            }
            tw[k] = best; ti[k] = bi;
            mask |= (1u << bi);
        }
        // Softmax denominator cancels against p=1 renorm.
        const float m = tw[0];
        float s = 0.f;
        #pragma unroll
        for (int k = 0; k < 4; k++) { tw[k] = expf(tw[k] - m); s += tw[k]; }
        const float inv = 1.0f / s;
        #pragma unroll
        for (int k = 0; k < 4; k++) {
            out[token * 4 + k] = tw[k] * inv;
            if (idx_off >= 0) out[idx_off + token * 4 + k] = (float)ti[k];
        }
    }
}

extern "C" void kernel_launch(void* const* d_in, const int* in_sizes, int n_in,
                              void* d_out, int out_size)
{
    const float* x = (const float*)d_in[0];
    const float* w = (const float*)d_in[1];

    const int H  = in_sizes[1] / NE;     // 6144
    const int T  = in_sizes[0] / H;      // 8192
    const int H4 = H / 4;                // 1536 float4 per row

    const int idx_off = (out_size >= T * 8) ? (T * 4) : -1;

    const int warps  = (T + 3) / 4;      // 2048
    const int blocks = (warps + 3) / 4;  // 512 CTAs of 128 threads
    router_kernel<<<blocks, 128>>>(x, w, (float*)d_out, T, H4, idx_off);
}